// round 2
// baseline (speedup 1.0000x reference)
#include <cuda_runtime.h>
#include <math.h>

// ---------------- problem constants ----------------
#define TT 128          // timesteps
#define FF 64           // input features
#define H1V 32          // layer1 hidden
#define G1 128          // 4*H1
#define XH1 96          // FF + H1
#define S1 8            // samples per warp, layer1
#define W1PB 4          // warps per block, layer1

#define H2V 16          // layer2 hidden
#define G2 64           // 4*H2
#define XH2 80          // 64 + H2
#define W2PB 4          // warps per block, layer2

#define MAXB 4096

// ---------------- scratch (no cudaMalloc allowed) ----------------
__device__ float g_h1[(size_t)MAXB * TT * 64];  // layer1 bidi output [B][T][64]
__device__ float g_h2[MAXB * 32];               // layer2 concat [B][32]

typedef unsigned long long u64;

// ---------------- f32x2 helpers (Blackwell packed fp32 FMA) ----------------
__device__ __forceinline__ u64 pack2(float a, float b) {
    u64 r; asm("mov.b64 %0, {%1,%2};" : "=l"(r) : "f"(a), "f"(b)); return r;
}
__device__ __forceinline__ void unpack2(u64 v, float &a, float &b) {
    asm("mov.b64 {%0,%1}, %2;" : "=f"(a), "=f"(b) : "l"(v));
}
__device__ __forceinline__ void ffma2(u64 &d, u64 a, u64 b) {
    asm("fma.rn.f32x2 %0, %1, %2, %0;" : "+l"(d) : "l"(a), "l"(b));
}

// ---------------- activations ----------------
__device__ __forceinline__ float sigf(float x) {
    return 1.0f / (1.0f + __expf(-x));
}
__device__ __forceinline__ float tanh_f(float x) {
    return 1.0f - 2.0f / (__expf(2.0f * x) + 1.0f);
}

// ================= layer 1: bidirectional LSTM, H=32, return sequences ================
// grid (B/32, 2), block 128 (4 warps). Each warp owns 8 samples end-to-end.
// Lane j owns gate element j for all 4 gates; gates packed (i,f) / (g,o) as f32x2.
// x/h staged in SMEM pre-duplicated as (v,v) pairs so the inner loop is pure
// LDS.128 + FFMA2.
__global__ void __launch_bounds__(128) lstm1_kernel(
    const float* __restrict__ x,
    const float* __restrict__ Wf, const float* __restrict__ Uf, const float* __restrict__ bf,
    const float* __restrict__ Wb, const float* __restrict__ Ub, const float* __restrict__ bb)
{
    extern __shared__ float smem[];
    float* sW  = smem;                     // [96][128] = 48KB, [k][elem][gate]
    float* sXH = smem + XH1 * G1;          // [4 warps][8 samp][192] dup pairs = 24KB

    const int dir = blockIdx.y;
    const float* W    = dir ? Wb : Wf;
    const float* U    = dir ? Ub : Uf;
    const float* bias = dir ? bb : bf;

    const int tid = threadIdx.x;
    const int wrp = tid >> 5;
    const int j   = tid & 31;

    // stage combined [W;U] transposed: sW[k*128 + e*4 + g] = src[k][g*32+e]
    for (int idx = tid; idx < XH1 * G1; idx += 128) {
        int k = idx >> 7;
        int c = idx & 127;
        int e = c >> 2, g = c & 3;
        sW[idx] = (k < FF) ? W[k * G1 + g * H1V + e]
                           : U[(k - FF) * G1 + g * H1V + e];
    }
    __syncthreads();

    const u64 bif = pack2(bias[j],           bias[H1V + j]);
    const u64 bgo = pack2(bias[2 * H1V + j], bias[3 * H1V + j]);

    const int sampleBase = (blockIdx.x * W1PB + wrp) * S1;
    float* xh = sXH + wrp * (S1 * 2 * XH1);     // per-warp region, rows of 192 floats

    float cc[S1];
    #pragma unroll
    for (int s = 0; s < S1; s++) {
        cc[s] = 0.0f;
        xh[s * 192 + (FF + j) * 2]     = 0.0f;  // h = 0 (dup pair)
        xh[s * 192 + (FF + j) * 2 + 1] = 0.0f;
    }
    __syncwarp();

    const float* xbase = x + (size_t)sampleBase * TT * FF;

    for (int t = 0; t < TT; t++) {
        const int tt = dir ? (TT - 1 - t) : t;

        // stage x_t duplicated: 8 samples * 16 float4 reads -> 4 per lane,
        // each expanded into two (v,v,w,w) float4 SMEM writes.
        #pragma unroll
        for (int r = 0; r < 4; r++) {
            int fl = j + r * 32;
            int s = fl >> 4, vec = fl & 15;
            float4 v = *((const float4*)(xbase + ((size_t)s * TT + tt) * FF) + vec);
            *(float4*)&xh[s * 192 + vec * 8]     = make_float4(v.x, v.x, v.y, v.y);
            *(float4*)&xh[s * 192 + vec * 8 + 4] = make_float4(v.z, v.z, v.w, v.w);
        }
        __syncwarp();

        u64 zif[S1], zgo[S1];
        #pragma unroll
        for (int s = 0; s < S1; s++) { zif[s] = bif; zgo[s] = bgo; }

        #pragma unroll 4
        for (int k4 = 0; k4 < XH1; k4 += 4) {
            const ulonglong2 w0 = *(const ulonglong2*)&sW[(k4 + 0) * G1 + j * 4];
            const ulonglong2 w1 = *(const ulonglong2*)&sW[(k4 + 1) * G1 + j * 4];
            const ulonglong2 w2 = *(const ulonglong2*)&sW[(k4 + 2) * G1 + j * 4];
            const ulonglong2 w3 = *(const ulonglong2*)&sW[(k4 + 3) * G1 + j * 4];
            #pragma unroll
            for (int s = 0; s < S1; s++) {
                const float* row = &xh[s * 192 + k4 * 2];
                const ulonglong2 xa = *(const ulonglong2*)row;        // (xk0,xk0),(xk1,xk1)
                const ulonglong2 xb = *(const ulonglong2*)(row + 4);  // (xk2,xk2),(xk3,xk3)
                ffma2(zif[s], w0.x, xa.x); ffma2(zgo[s], w0.y, xa.x);
                ffma2(zif[s], w1.x, xa.y); ffma2(zgo[s], w1.y, xa.y);
                ffma2(zif[s], w2.x, xb.x); ffma2(zgo[s], w2.y, xb.x);
                ffma2(zif[s], w3.x, xb.y); ffma2(zgo[s], w3.y, xb.y);
            }
        }

        __syncwarp();   // all lanes done reading x/h of this step
        float* outp = &g_h1[((size_t)sampleBase * TT + tt) * 64 + dir * H1V + j];
        #pragma unroll
        for (int s = 0; s < S1; s++) {
            float zi, zf, zg, zo;
            unpack2(zif[s], zi, zf);
            unpack2(zgo[s], zg, zo);
            const float ig = sigf(zi);
            const float fg = sigf(zf);
            const float gg = tanh_f(zg);
            const float og = sigf(zo);
            cc[s] = fg * cc[s] + ig * gg;
            const float h = og * tanh_f(cc[s]);
            xh[s * 192 + (FF + j) * 2]     = h;
            xh[s * 192 + (FF + j) * 2 + 1] = h;
            outp[(size_t)s * TT * 64] = h;
        }
        // next iteration's staging __syncwarp orders these h writes vs reads
    }
}

// ================= layer 2: bidirectional LSTM, H=16, return last h ================
// grid (B/32, 2), block 128. Lane: e = j&15 (gate elem), hw = j>>4 picks which
// 4 of the warp's 8 samples this lane serves. Same f32x2 + dup-SMEM scheme.
__global__ void __launch_bounds__(128) lstm2_kernel(
    const float* __restrict__ W2f, const float* __restrict__ U2f, const float* __restrict__ b2f,
    const float* __restrict__ W2b, const float* __restrict__ U2b, const float* __restrict__ b2b)
{
    __shared__ __align__(16) float sW[XH2 * G2];           // 20KB
    __shared__ __align__(16) float sXH[W2PB * 8 * 160];    // 20KB (dup rows of 160)

    const int dir = blockIdx.y;
    const float* W    = dir ? W2b : W2f;
    const float* U    = dir ? U2b : U2f;
    const float* bias = dir ? b2b : b2f;

    const int tid = threadIdx.x;
    const int wrp = tid >> 5;
    const int j   = tid & 31;
    const int e   = j & 15;
    const int hw  = j >> 4;

    for (int idx = tid; idx < XH2 * G2; idx += 128) {
        int k = idx >> 6;
        int c = idx & 63;
        int ee = c >> 2, g = c & 3;
        sW[idx] = (k < 64) ? W[k * G2 + g * H2V + ee]
                           : U[(k - 64) * G2 + g * H2V + ee];
    }
    __syncthreads();

    const u64 bif = pack2(bias[e],           bias[H2V + e]);
    const u64 bgo = pack2(bias[2 * H2V + e], bias[3 * H2V + e]);

    const int sampleBase = (blockIdx.x * W2PB + wrp) * 8;
    float* xh = sXH + wrp * (8 * 160);

    float cc[4], hh[4];
    #pragma unroll
    for (int s = 0; s < 4; s++) {
        cc[s] = 0.0f;
        hh[s] = 0.0f;
        xh[(hw * 4 + s) * 160 + (64 + e) * 2]     = 0.0f;
        xh[(hw * 4 + s) * 160 + (64 + e) * 2 + 1] = 0.0f;
    }
    __syncwarp();

    for (int t = 0; t < TT; t++) {
        const int tt = dir ? (TT - 1 - t) : t;

        #pragma unroll
        for (int r = 0; r < 4; r++) {
            int fl = j + r * 32;
            int s = fl >> 4, vec = fl & 15;
            float4 v = *((const float4*)(g_h1 + ((size_t)(sampleBase + s) * TT + tt) * 64) + vec);
            *(float4*)&xh[s * 160 + vec * 8]     = make_float4(v.x, v.x, v.y, v.y);
            *(float4*)&xh[s * 160 + vec * 8 + 4] = make_float4(v.z, v.z, v.w, v.w);
        }
        __syncwarp();

        u64 zif[4], zgo[4];
        #pragma unroll
        for (int s = 0; s < 4; s++) { zif[s] = bif; zgo[s] = bgo; }

        #pragma unroll 4
        for (int k4 = 0; k4 < XH2; k4 += 4) {
            const ulonglong2 w0 = *(const ulonglong2*)&sW[(k4 + 0) * G2 + e * 4];
            const ulonglong2 w1 = *(const ulonglong2*)&sW[(k4 + 1) * G2 + e * 4];
            const ulonglong2 w2 = *(const ulonglong2*)&sW[(k4 + 2) * G2 + e * 4];
            const ulonglong2 w3 = *(const ulonglong2*)&sW[(k4 + 3) * G2 + e * 4];
            #pragma unroll
            for (int s = 0; s < 4; s++) {
                const float* row = &xh[(hw * 4 + s) * 160 + k4 * 2];
                const ulonglong2 xa = *(const ulonglong2*)row;
                const ulonglong2 xb = *(const ulonglong2*)(row + 4);
                ffma2(zif[s], w0.x, xa.x); ffma2(zgo[s], w0.y, xa.x);
                ffma2(zif[s], w1.x, xa.y); ffma2(zgo[s], w1.y, xa.y);
                ffma2(zif[s], w2.x, xb.x); ffma2(zgo[s], w2.y, xb.x);
                ffma2(zif[s], w3.x, xb.y); ffma2(zgo[s], w3.y, xb.y);
            }
        }

        __syncwarp();
        #pragma unroll
        for (int s = 0; s < 4; s++) {
            float zi, zf, zg, zo;
            unpack2(zif[s], zi, zf);
            unpack2(zgo[s], zg, zo);
            const float ig = sigf(zi);
            const float fg = sigf(zf);
            const float gg = tanh_f(zg);
            const float og = sigf(zo);
            cc[s] = fg * cc[s] + ig * gg;
            hh[s] = og * tanh_f(cc[s]);
            xh[(hw * 4 + s) * 160 + (64 + e) * 2]     = hh[s];
            xh[(hw * 4 + s) * 160 + (64 + e) * 2 + 1] = hh[s];
        }
    }

    // final h: fwd -> cols [0,16), bwd -> cols [16,32)
    #pragma unroll
    for (int s = 0; s < 4; s++)
        g_h2[(sampleBase + hw * 4 + s) * 32 + dir * H2V + e] = hh[s];
}

// ================= head: dense(8)+swish, dense(2)+sigmoid ================
__global__ void head_kernel(
    const float* __restrict__ W3, const float* __restrict__ b3,
    const float* __restrict__ W4, const float* __restrict__ b4,
    float* __restrict__ out, int B)
{
    const int b = blockIdx.x * blockDim.x + threadIdx.x;
    if (b >= B) return;

    float xv[32];
    #pragma unroll
    for (int i = 0; i < 32; i++) xv[i] = g_h2[b * 32 + i];

    float y[8];
    #pragma unroll
    for (int o = 0; o < 8; o++) {
        float acc = b3[o];
        #pragma unroll
        for (int k = 0; k < 32; k++)
            acc = fmaf(xv[k], W3[k * 8 + o], acc);
        y[o] = acc * sigf(acc);   // swish
    }

    #pragma unroll
    for (int m = 0; m < 2; m++) {
        float acc = b4[m];
        #pragma unroll
        for (int o = 0; o < 8; o++)
            acc = fmaf(y[o], W4[o * 2 + m], acc);
        out[b * 2 + m] = sigf(acc);
    }
}

// ================= launch ================
extern "C" void kernel_launch(void* const* d_in, const int* in_sizes, int n_in,
                              void* d_out, int out_size)
{
    const float* x   = (const float*)d_in[0];
    const float* W1f = (const float*)d_in[1];
    const float* U1f = (const float*)d_in[2];
    const float* b1f = (const float*)d_in[3];
    const float* W1b = (const float*)d_in[4];
    const float* U1b = (const float*)d_in[5];
    const float* b1b = (const float*)d_in[6];
    const float* W2f = (const float*)d_in[7];
    const float* U2f = (const float*)d_in[8];
    const float* b2f = (const float*)d_in[9];
    const float* W2b = (const float*)d_in[10];
    const float* U2b = (const float*)d_in[11];
    const float* b2b = (const float*)d_in[12];
    const float* W3  = (const float*)d_in[13];
    const float* b3  = (const float*)d_in[14];
    const float* W4  = (const float*)d_in[15];
    const float* b4  = (const float*)d_in[16];
    float* out = (float*)d_out;

    const int B = in_sizes[0] / (TT * FF);   // 4096

    const int smem1 = (XH1 * G1 + W1PB * S1 * 2 * XH1) * (int)sizeof(float);  // 72KB
    cudaFuncSetAttribute(lstm1_kernel, cudaFuncAttributeMaxDynamicSharedMemorySize, smem1);

    lstm1_kernel<<<dim3(B / (W1PB * S1), 2), 128, smem1>>>(
        x, W1f, U1f, b1f, W1b, U1b, b1b);

    lstm2_kernel<<<dim3(B / (W2PB * 8), 2), 128>>>(
        W2f, U2f, b2f, W2b, U2b, b2b);

    head_kernel<<<(B + 255) / 256, 256>>>(W3, b3, W4, b4, out, B);
}